// round 12
// baseline (speedup 1.0000x reference)
#include <cuda_runtime.h>
#include <cuda_bf16.h>
#include <cstdint>

#define N_NODES 50000
#define N_EDGES_MAX 800000
#define IN_DIM  256
#define OUT_DIM 256
#define M_PAD   50176          // 392 * 128
#define NROWS   (M_PAD / 128)  // 392 tile rows
#define GTICK_NODES 16
#define NGTICK  (M_PAD / GTICK_NODES)   // 3136 gather tickets
#define DONE_PER_ROW 8                  // 8 tickets per 128-node row

// ---------------------------------------------------------------------------
// Device-global scratch (allocation-free).
// ---------------------------------------------------------------------------
__device__ int g_deg[N_NODES];
__device__ int g_off[N_NODES + 1];
__device__ int g_cur[N_NODES];
__device__ int g_esrc[N_EDGES_MAX];
#define SCAN_BLK 512
#define SCAN_NB  98            // 98*512 = 50176 >= N_NODES
__device__ int g_bsum[SCAN_NB];
__device__ unsigned g_tile_ctr;
__device__ unsigned g_gath_ctr;
__device__ unsigned g_done[NROWS];
// bf16 split planes of the aggregated features (A) and transposed weight (B)
// rows >= N_NODES are never written -> remain zero (device globals zero-init)
__device__ __align__(16) __nv_bfloat16 g_hiA[(size_t)M_PAD * IN_DIM];
__device__ __align__(16) __nv_bfloat16 g_loA[(size_t)M_PAD * IN_DIM];
__device__ __align__(16) __nv_bfloat16 g_hiB[(size_t)OUT_DIM * IN_DIM];  // [n][k]
__device__ __align__(16) __nv_bfloat16 g_loB[(size_t)OUT_DIM * IN_DIM];  // [n][k]

// ---------------------------------------------------------------------------
// helpers
// ---------------------------------------------------------------------------
__device__ __forceinline__ uint32_t smem_to_u32(const void* p) {
    uint32_t a;
    asm("{ .reg .u64 t; cvta.to.shared.u64 t, %1; cvt.u32.u64 %0, t; }"
        : "=r"(a) : "l"(p));
    return a;
}
__device__ __forceinline__ void ldm4(uint32_t* r, uint32_t addr) {
    asm volatile("ldmatrix.sync.aligned.m8n8.x4.shared.b16 {%0,%1,%2,%3}, [%4];"
                 : "=r"(r[0]), "=r"(r[1]), "=r"(r[2]), "=r"(r[3]) : "r"(addr));
}
__device__ __forceinline__ void mma16816(float* c, const uint32_t* a,
                                         uint32_t b0, uint32_t b1) {
    asm volatile(
        "mma.sync.aligned.m16n8k16.row.col.f32.bf16.bf16.f32 "
        "{%0,%1,%2,%3}, {%4,%5,%6,%7}, {%8,%9}, {%0,%1,%2,%3};"
        : "+f"(c[0]), "+f"(c[1]), "+f"(c[2]), "+f"(c[3])
        : "r"(a[0]), "r"(a[1]), "r"(a[2]), "r"(a[3]), "r"(b0), "r"(b1));
}
__device__ __forceinline__ void acc4(float4& a, float4 v) {
    a.x += v.x; a.y += v.y; a.z += v.z; a.w += v.w;
}
__device__ __forceinline__ void split4(float4 v, uint2& hi, uint2& lo) {
    __nv_bfloat16 h0 = __float2bfloat16(v.x);
    __nv_bfloat16 h1 = __float2bfloat16(v.y);
    __nv_bfloat16 h2 = __float2bfloat16(v.z);
    __nv_bfloat16 h3 = __float2bfloat16(v.w);
    __nv_bfloat16 l0 = __float2bfloat16(v.x - __bfloat162float(h0));
    __nv_bfloat16 l1 = __float2bfloat16(v.y - __bfloat162float(h1));
    __nv_bfloat16 l2 = __float2bfloat16(v.z - __bfloat162float(h2));
    __nv_bfloat16 l3 = __float2bfloat16(v.w - __bfloat162float(h3));
    __nv_bfloat162 hA = __nv_bfloat162(h0, h1), hB = __nv_bfloat162(h2, h3);
    __nv_bfloat162 lA = __nv_bfloat162(l0, l1), lB = __nv_bfloat162(l2, l3);
    hi.x = *reinterpret_cast<uint32_t*>(&hA); hi.y = *reinterpret_cast<uint32_t*>(&hB);
    lo.x = *reinterpret_cast<uint32_t*>(&lA); lo.y = *reinterpret_cast<uint32_t*>(&lB);
}

// ---------------------------------------------------------------------------
// Kernel 1: convert W -> transposed bf16 hi/lo planes (B[n][k] = W[k][n]),
// fused with: zero degree histogram + ticket/readiness reset.
// ---------------------------------------------------------------------------
__global__ __launch_bounds__(256) void convw_zero_kernel(const float* __restrict__ W) {
    int idx = blockIdx.x * blockDim.x + threadIdx.x;   // 0..65535
    if (idx == 0) { g_tile_ctr = 0; g_gath_ctr = 0; }
    if (idx < NROWS) g_done[idx] = 0;
    if (idx < N_NODES) g_deg[idx] = 0;
    if (idx >= IN_DIM * OUT_DIM) return;
    int k = idx >> 8;
    int n = idx & 255;
    float w = W[idx];
    __nv_bfloat16 h = __float2bfloat16(w);
    __nv_bfloat16 l = __float2bfloat16(w - __bfloat162float(h));
    g_hiB[n * IN_DIM + k] = h;
    g_loB[n * IN_DIM + k] = l;
}

// ---------------------------------------------------------------------------
// Kernel 2: degree histogram over dst
// ---------------------------------------------------------------------------
__global__ void hist_kernel(const int* __restrict__ dst, int n_edges) {
    int e = blockIdx.x * blockDim.x + threadIdx.x;
    if (e < n_edges) atomicAdd(&g_deg[dst[e]], 1);
}

// ---------------------------------------------------------------------------
// Kernels 3a/3c: parallel exclusive scan of degrees -> offsets + cursors
// ---------------------------------------------------------------------------
__global__ __launch_bounds__(SCAN_BLK) void scan_a_kernel() {
    __shared__ int sh[SCAN_BLK];
    int t = threadIdx.x;
    int i = blockIdx.x * SCAN_BLK + t;
    sh[t] = (i < N_NODES) ? g_deg[i] : 0;
    __syncthreads();
    for (int s = SCAN_BLK / 2; s > 0; s >>= 1) {
        if (t < s) sh[t] += sh[t + s];
        __syncthreads();
    }
    if (t == 0) g_bsum[blockIdx.x] = sh[0];
}

__global__ __launch_bounds__(SCAN_BLK) void scan_c_kernel() {
    __shared__ int sh[SCAN_BLK];
    __shared__ int s_bpre;
    int t = threadIdx.x;
    int i = blockIdx.x * SCAN_BLK + t;

    if (t < 128) {
        int v = (t < blockIdx.x && t < SCAN_NB) ? g_bsum[t] : 0;
        sh[t] = v;
    }
    __syncthreads();
    if (t < 64) sh[t] += sh[t + 64];
    __syncthreads();
    if (t < 32) {
        int v = sh[t] + sh[t + 32];
        for (int o = 16; o > 0; o >>= 1) v += __shfl_down_sync(0xFFFFFFFF, v, o);
        if (t == 0) s_bpre = v;
    }
    __syncthreads();
    const int bpre = s_bpre;
    __syncthreads();

    int v = (i < N_NODES) ? g_deg[i] : 0;
    sh[t] = v;
    __syncthreads();
    for (int d = 1; d < SCAN_BLK; d <<= 1) {
        int x = (t >= d) ? sh[t - d] : 0;
        __syncthreads();
        sh[t] += x;
        __syncthreads();
    }
    int off = bpre + sh[t] - v;
    if (i < N_NODES) {
        g_off[i] = off;
        g_cur[i] = off;
    }
    if (i == N_NODES - 1) g_off[N_NODES] = off + v;
}

// ---------------------------------------------------------------------------
// Kernel 4: fill CSR edge lists
// ---------------------------------------------------------------------------
__global__ void fill_kernel(const int* __restrict__ src,
                            const int* __restrict__ dst, int n_edges) {
    int e = blockIdx.x * blockDim.x + threadIdx.x;
    if (e < n_edges) {
        int d = dst[e];
        int p = atomicAdd(&g_cur[d], 1);
        g_esrc[p] = src[e];
    }
}

// ---------------------------------------------------------------------------
// Kernel 5 (FUSED): persistent gather + GEMM with tile-row readiness.
// Phase 1: gather tickets (16 nodes each; 8 warps x 4 node-halves).
// Phase 2: GEMM tiles; spin until the tile's 128 node-rows are gathered.
// ---------------------------------------------------------------------------
#define SWX(o) ((o) ^ (((o) >> 3) & 0x70))
#define NTILES (2 * NROWS)   // 784

__global__ __launch_bounds__(256, 2) void fused_kernel(const float* __restrict__ feature,
                                                       float* __restrict__ out) {
    __shared__ __align__(16) uint8_t sA[128 * 128];
    __shared__ __align__(16) uint8_t sB[128 * 128];
    __shared__ unsigned s_tick;

    const int tid  = threadIdx.x;
    const int lane = tid & 31;
    const int wid  = tid >> 5;

    // ================= Phase 1: gather =================
    for (;;) {
        __syncthreads();
        if (tid == 0) s_tick = atomicAdd(&g_gath_ctr, 1u);
        __syncthreads();
        const unsigned t = s_tick;
        if (t >= NGTICK) break;

#pragma unroll 1
        for (int j = 0; j < 4; ++j) {
            int gw   = (int)t * 32 + j * 8 + wid;   // node-half index
            int node = gw >> 1;
            int half = gw & 1;
            if (node >= N_NODES) continue;

            int beg = g_off[node];
            int end = g_off[node + 1];
            const float4* fbase =
                reinterpret_cast<const float4*>(feature) + half * 32 + lane;

            float4 acc = make_float4(0.f, 0.f, 0.f, 0.f);
            int i = beg;
            for (; i + 4 <= end; i += 4) {
                int s0 = g_esrc[i];
                int s1 = g_esrc[i + 1];
                int s2 = g_esrc[i + 2];
                int s3 = g_esrc[i + 3];
                float4 v0 = fbase[(size_t)s0 * 64];
                float4 v1 = fbase[(size_t)s1 * 64];
                float4 v2 = fbase[(size_t)s2 * 64];
                float4 v3 = fbase[(size_t)s3 * 64];
                acc4(acc, v0); acc4(acc, v1); acc4(acc, v2); acc4(acc, v3);
            }
            for (; i < end; ++i) {
                acc4(acc, fbase[(size_t)g_esrc[i] * 64]);
            }

            uint2 h, l;
            split4(acc, h, l);
            size_t base = (size_t)node * IN_DIM + half * 128;
            *reinterpret_cast<uint2*>(g_hiA + base + 4 * lane) = h;
            *reinterpret_cast<uint2*>(g_loA + base + 4 * lane) = l;
        }

        __syncthreads();
        __threadfence();
        if (tid == 0) atomicAdd(&g_done[t >> 3], 1u);   // 8 tickets per row
    }

    // ================= Phase 2: GEMM =================
    const int warpM = wid & 3;
    const int warpN = wid >> 2;
    const uint32_t sAu = smem_to_u32(sA);
    const uint32_t sBu = smem_to_u32(sB);
    const int aRow  = warpM * 32 + (lane & 15);
    const uint32_t aHalf = (uint32_t)((lane >> 4) << 4);
    const int bRowBase = warpN * 64 + (lane & 7) + (((lane >> 4) & 1) << 3);
    const uint32_t bHalf = (uint32_t)(((lane >> 3) & 1) << 4);
    const int groupID = lane >> 2;
    const int tig     = lane & 3;

    for (;;) {
        __syncthreads();
        if (tid == 0) s_tick = atomicAdd(&g_tile_ctr, 1u);
        __syncthreads();
        const unsigned t = s_tick;
        if (t >= NTILES) break;
        const int m = (int)(t >> 1);
        const int m0 = m * 128;
        const int n0 = (int)(t & 1) * 128;

        // wait for this tile-row's gather to complete
        if (tid == 0) {
            while (*((volatile unsigned*)&g_done[m]) < (unsigned)DONE_PER_ROW) { }
            __threadfence();
        }
        __syncthreads();

        float acc[2][8][4];
#pragma unroll
        for (int mi = 0; mi < 2; mi++)
#pragma unroll
            for (int nf = 0; nf < 8; nf++)
#pragma unroll
                for (int q = 0; q < 4; q++) acc[mi][nf][q] = 0.f;

#pragma unroll 1
        for (int it = 0; it < 12; ++it) {
            const int pass = it >> 2;
            const int k0   = (it & 3) * 64;
            const __nv_bfloat16* Ap = (pass < 2) ? g_hiA : g_loA;
            const __nv_bfloat16* Bp = (pass == 1) ? g_loB : g_hiB;

#pragma unroll
            for (int l = 0; l < 4; ++l) {
                int idx = tid + 256 * l;
                int row = idx >> 3;
                int u   = idx & 7;
                uint4 v = *reinterpret_cast<const uint4*>(
                              Ap + (size_t)(m0 + row) * IN_DIM + k0 + u * 8);
                *reinterpret_cast<uint4*>(sA + SWX(row * 128 + u * 16)) = v;
            }
#pragma unroll
            for (int l = 0; l < 4; ++l) {
                int idx = tid + 256 * l;
                int row = idx >> 3;
                int u   = idx & 7;
                uint4 v = *reinterpret_cast<const uint4*>(
                              Bp + (size_t)(n0 + row) * IN_DIM + k0 + u * 8);
                *reinterpret_cast<uint4*>(sB + SWX(row * 128 + u * 16)) = v;
            }
            __syncthreads();

#pragma unroll
            for (int ks = 0; ks < 4; ++ks) {
                const uint32_t koff = (uint32_t)(ks * 32);
                uint32_t afr[2][4];
#pragma unroll
                for (int mi = 0; mi < 2; mi++) {
                    const int r = aRow + mi * 16;
                    uint32_t addr = sAu + (uint32_t)(r * 128)
                                  + ((koff + aHalf) ^ ((uint32_t)((r << 4) & 0x70)));
                    ldm4(afr[mi], addr);
                }
#pragma unroll
                for (int nf2 = 0; nf2 < 4; nf2++) {
                    const int bRow = bRowBase + nf2 * 16;
                    uint32_t baddr = sBu + (uint32_t)(bRow * 128)
                                   + ((koff + bHalf) ^ ((uint32_t)((bRow << 4) & 0x70)));
                    uint32_t bfr[4];
                    ldm4(bfr, baddr);
#pragma unroll
                    for (int mi = 0; mi < 2; mi++) {
                        mma16816(acc[mi][nf2 * 2],     afr[mi], bfr[0], bfr[1]);
                        mma16816(acc[mi][nf2 * 2 + 1], afr[mi], bfr[2], bfr[3]);
                    }
                }
            }
            __syncthreads();
        }

        // epilogue
#pragma unroll
        for (int mi = 0; mi < 2; mi++) {
#pragma unroll
            for (int nf = 0; nf < 8; nf++) {
                int row0 = m0 + warpM * 32 + mi * 16 + groupID;
                int col  = n0 + warpN * 64 + nf * 8 + tig * 2;
                if (row0 < N_NODES) {
                    float2 v0 = make_float2(acc[mi][nf][0], acc[mi][nf][1]);
                    *reinterpret_cast<float2*>(out + (size_t)row0 * OUT_DIM + col) = v0;
                }
                int row1 = row0 + 8;
                if (row1 < N_NODES) {
                    float2 v1 = make_float2(acc[mi][nf][2], acc[mi][nf][3]);
                    *reinterpret_cast<float2*>(out + (size_t)row1 * OUT_DIM + col) = v1;
                }
            }
        }
    }
}

// ---------------------------------------------------------------------------
extern "C" void kernel_launch(void* const* d_in, const int* in_sizes, int n_in,
                              void* d_out, int out_size) {
    const float* feature = (const float*)d_in[0];
    const float* weight  = (const float*)d_in[1];
    const int*   src     = (const int*)d_in[2];
    const int*   dst     = (const int*)d_in[3];
    float*       out     = (float*)d_out;
    const int n_edges = in_sizes[2];

    convw_zero_kernel<<<(IN_DIM * OUT_DIM + 255) / 256, 256>>>(weight);
    hist_kernel<<<(n_edges + 255) / 256, 256>>>(dst, n_edges);
    scan_a_kernel<<<SCAN_NB, SCAN_BLK>>>();
    scan_c_kernel<<<SCAN_NB, SCAN_BLK>>>();
    fill_kernel<<<(n_edges + 255) / 256, 256>>>(src, dst, n_edges);
    fused_kernel<<<296, 256>>>(feature, out);
}

// round 13
// speedup vs baseline: 1.8606x; 1.8606x over previous
#include <cuda_runtime.h>
#include <cuda_bf16.h>
#include <cuda_fp16.h>
#include <cstdint>

#define N_NODES 50000
#define N_EDGES_MAX 800000
#define IN_DIM  256
#define OUT_DIM 256
#define M_PAD   50176          // 392 * 128

// ---------------------------------------------------------------------------
// Device-global scratch (allocation-free).
// ---------------------------------------------------------------------------
__device__ int g_deg[N_NODES];
__device__ int g_off[N_NODES + 1];
__device__ int g_cur[N_NODES];
__device__ int g_esrc[N_EDGES_MAX];
#define SCAN_BLK 512
#define SCAN_NB  98            // 98*512 = 50176 >= N_NODES
__device__ int g_bsum[SCAN_NB];
__device__ unsigned g_tile_ctr;
// fp16 copy of feature (halves gather traffic)
__device__ __align__(16) __half g_f16[(size_t)N_NODES * IN_DIM];
// bf16 split planes of the aggregated features (A) and transposed weight (B)
// rows >= N_NODES are never written -> remain zero (device globals zero-init)
__device__ __align__(16) __nv_bfloat16 g_hiA[(size_t)M_PAD * IN_DIM];
__device__ __align__(16) __nv_bfloat16 g_loA[(size_t)M_PAD * IN_DIM];
__device__ __align__(16) __nv_bfloat16 g_hiB[(size_t)OUT_DIM * IN_DIM];  // [n][k]
__device__ __align__(16) __nv_bfloat16 g_loB[(size_t)OUT_DIM * IN_DIM];  // [n][k]

// ---------------------------------------------------------------------------
// helpers
// ---------------------------------------------------------------------------
__device__ __forceinline__ uint32_t smem_to_u32(const void* p) {
    uint32_t a;
    asm("{ .reg .u64 t; cvta.to.shared.u64 t, %1; cvt.u32.u64 %0, t; }"
        : "=r"(a) : "l"(p));
    return a;
}
__device__ __forceinline__ void ldm4(uint32_t* r, uint32_t addr) {
    asm volatile("ldmatrix.sync.aligned.m8n8.x4.shared.b16 {%0,%1,%2,%3}, [%4];"
                 : "=r"(r[0]), "=r"(r[1]), "=r"(r[2]), "=r"(r[3]) : "r"(addr));
}
__device__ __forceinline__ void mma16816(float* c, const uint32_t* a,
                                         uint32_t b0, uint32_t b1) {
    asm volatile(
        "mma.sync.aligned.m16n8k16.row.col.f32.bf16.bf16.f32 "
        "{%0,%1,%2,%3}, {%4,%5,%6,%7}, {%8,%9}, {%0,%1,%2,%3};"
        : "+f"(c[0]), "+f"(c[1]), "+f"(c[2]), "+f"(c[3])
        : "r"(a[0]), "r"(a[1]), "r"(a[2]), "r"(a[3]), "r"(b0), "r"(b1));
}

// ---------------------------------------------------------------------------
// Kernel 0: convert feature -> fp16 (8 elements per thread)
// ---------------------------------------------------------------------------
__global__ __launch_bounds__(256) void convf_kernel(const float* __restrict__ feature) {
    int i = blockIdx.x * blockDim.x + threadIdx.x;
    const int n8 = (N_NODES * IN_DIM) / 8;
    if (i >= n8) return;
    float4 a = reinterpret_cast<const float4*>(feature)[2 * i];
    float4 b = reinterpret_cast<const float4*>(feature)[2 * i + 1];
    __half2 h0 = __floats2half2_rn(a.x, a.y);
    __half2 h1 = __floats2half2_rn(a.z, a.w);
    __half2 h2 = __floats2half2_rn(b.x, b.y);
    __half2 h3 = __floats2half2_rn(b.z, b.w);
    uint4 v;
    v.x = *reinterpret_cast<uint32_t*>(&h0);
    v.y = *reinterpret_cast<uint32_t*>(&h1);
    v.z = *reinterpret_cast<uint32_t*>(&h2);
    v.w = *reinterpret_cast<uint32_t*>(&h3);
    reinterpret_cast<uint4*>(g_f16)[i] = v;
}

// ---------------------------------------------------------------------------
// Kernel 1: convert W -> transposed bf16 hi/lo planes (B[n][k] = W[k][n]),
// fused with: zero degree histogram + GEMM tile-ticket reset.
// ---------------------------------------------------------------------------
__global__ __launch_bounds__(256) void convw_zero_kernel(const float* __restrict__ W) {
    int idx = blockIdx.x * blockDim.x + threadIdx.x;   // 0..65535
    if (idx == 0) g_tile_ctr = 0;
    if (idx < N_NODES) g_deg[idx] = 0;
    if (idx >= IN_DIM * OUT_DIM) return;
    int k = idx >> 8;
    int n = idx & 255;
    float w = W[idx];
    __nv_bfloat16 h = __float2bfloat16(w);
    __nv_bfloat16 l = __float2bfloat16(w - __bfloat162float(h));
    g_hiB[n * IN_DIM + k] = h;
    g_loB[n * IN_DIM + k] = l;
}

// ---------------------------------------------------------------------------
// Kernel 2: degree histogram over dst
// ---------------------------------------------------------------------------
__global__ void hist_kernel(const int* __restrict__ dst, int n_edges) {
    int e = blockIdx.x * blockDim.x + threadIdx.x;
    if (e < n_edges) atomicAdd(&g_deg[dst[e]], 1);
}

// ---------------------------------------------------------------------------
// Kernels 3a/3c: parallel exclusive scan of degrees -> offsets + cursors
// ---------------------------------------------------------------------------
__global__ __launch_bounds__(SCAN_BLK) void scan_a_kernel() {
    __shared__ int sh[SCAN_BLK];
    int t = threadIdx.x;
    int i = blockIdx.x * SCAN_BLK + t;
    sh[t] = (i < N_NODES) ? g_deg[i] : 0;
    __syncthreads();
    for (int s = SCAN_BLK / 2; s > 0; s >>= 1) {
        if (t < s) sh[t] += sh[t + s];
        __syncthreads();
    }
    if (t == 0) g_bsum[blockIdx.x] = sh[0];
}

__global__ __launch_bounds__(SCAN_BLK) void scan_c_kernel() {
    __shared__ int sh[SCAN_BLK];
    __shared__ int s_bpre;
    int t = threadIdx.x;
    int i = blockIdx.x * SCAN_BLK + t;

    if (t < 128) {
        int v = (t < blockIdx.x && t < SCAN_NB) ? g_bsum[t] : 0;
        sh[t] = v;
    }
    __syncthreads();
    if (t < 64) sh[t] += sh[t + 64];
    __syncthreads();
    if (t < 32) {
        int v = sh[t] + sh[t + 32];
        for (int o = 16; o > 0; o >>= 1) v += __shfl_down_sync(0xFFFFFFFF, v, o);
        if (t == 0) s_bpre = v;
    }
    __syncthreads();
    const int bpre = s_bpre;
    __syncthreads();

    int v = (i < N_NODES) ? g_deg[i] : 0;
    sh[t] = v;
    __syncthreads();
    for (int d = 1; d < SCAN_BLK; d <<= 1) {
        int x = (t >= d) ? sh[t - d] : 0;
        __syncthreads();
        sh[t] += x;
        __syncthreads();
    }
    int off = bpre + sh[t] - v;
    if (i < N_NODES) {
        g_off[i] = off;
        g_cur[i] = off;
    }
    if (i == N_NODES - 1) g_off[N_NODES] = off + v;
}

// ---------------------------------------------------------------------------
// Kernel 4: fill CSR edge lists
// ---------------------------------------------------------------------------
__global__ void fill_kernel(const int* __restrict__ src,
                            const int* __restrict__ dst, int n_edges) {
    int e = blockIdx.x * blockDim.x + threadIdx.x;
    if (e < n_edges) {
        int d = dst[e];
        int p = atomicAdd(&g_cur[d], 1);
        g_esrc[p] = src[e];
    }
}

// ---------------------------------------------------------------------------
// Kernel 5: gather (fp16 features) -> bf16 hi/lo planes.
// TWO warps per node (half row each), 1 uint2 (8B = 4 halves) per lane per
// edge, 4-edge unroll, f32 accumulation. Same parallelism/MLP as the fp32
// champion; only bytes halve.
// ---------------------------------------------------------------------------
__device__ __forceinline__ void acch4(float* a, uint2 v) {
    __half2 h0 = *reinterpret_cast<__half2*>(&v.x);
    __half2 h1 = *reinterpret_cast<__half2*>(&v.y);
    float2 f0 = __half22float2(h0);
    float2 f1 = __half22float2(h1);
    a[0] += f0.x; a[1] += f0.y; a[2] += f1.x; a[3] += f1.y;
}

__global__ __launch_bounds__(256) void gather_kernel() {
    int gw   = (blockIdx.x * blockDim.x + threadIdx.x) >> 5;
    int node = gw >> 1;
    int half = gw & 1;
    int lane = threadIdx.x & 31;
    if (node >= N_NODES) return;

    int beg = g_off[node];
    int end = g_off[node + 1];

    // lane owns 4 fp16 elements: one uint2 per row (row = 64 uint2)
    const uint2* fbase = reinterpret_cast<const uint2*>(g_f16) + half * 32 + lane;

    float acc[4];
    acc[0] = acc[1] = acc[2] = acc[3] = 0.f;

    int i = beg;
    for (; i + 4 <= end; i += 4) {
        int s0 = g_esrc[i];
        int s1 = g_esrc[i + 1];
        int s2 = g_esrc[i + 2];
        int s3 = g_esrc[i + 3];
        uint2 v0 = fbase[(size_t)s0 * 64];
        uint2 v1 = fbase[(size_t)s1 * 64];
        uint2 v2 = fbase[(size_t)s2 * 64];
        uint2 v3 = fbase[(size_t)s3 * 64];
        acch4(acc, v0); acch4(acc, v1); acch4(acc, v2); acch4(acc, v3);
    }
    for (; i < end; ++i) {
        acch4(acc, fbase[(size_t)g_esrc[i] * 64]);
    }

    // split into bf16 hi/lo (4 floats -> 2x uint2)
    uint2 h, l;
    {
        __nv_bfloat16 h0 = __float2bfloat16(acc[0]);
        __nv_bfloat16 h1 = __float2bfloat16(acc[1]);
        __nv_bfloat16 h2 = __float2bfloat16(acc[2]);
        __nv_bfloat16 h3 = __float2bfloat16(acc[3]);
        __nv_bfloat16 l0 = __float2bfloat16(acc[0] - __bfloat162float(h0));
        __nv_bfloat16 l1 = __float2bfloat16(acc[1] - __bfloat162float(h1));
        __nv_bfloat16 l2 = __float2bfloat16(acc[2] - __bfloat162float(h2));
        __nv_bfloat16 l3 = __float2bfloat16(acc[3] - __bfloat162float(h3));
        __nv_bfloat162 hA = __nv_bfloat162(h0, h1), hB = __nv_bfloat162(h2, h3);
        __nv_bfloat162 lA = __nv_bfloat162(l0, l1), lB = __nv_bfloat162(l2, l3);
        h.x = *reinterpret_cast<uint32_t*>(&hA); h.y = *reinterpret_cast<uint32_t*>(&hB);
        l.x = *reinterpret_cast<uint32_t*>(&lA); l.y = *reinterpret_cast<uint32_t*>(&lB);
    }
    size_t base = (size_t)node * IN_DIM + half * 128;
    *reinterpret_cast<uint2*>(g_hiA + base + 4 * lane) = h;
    *reinterpret_cast<uint2*>(g_loA + base + 4 * lane) = l;
}

// ---------------------------------------------------------------------------
// Kernel 6: bf16 HMMA GEMM, 3 error-compensated passes, persistent CTAs with
// dynamic tile ticket. Tile 128x128, 8 warps (4M x 2N), K-chunk 64.
// ---------------------------------------------------------------------------
#define SWX(o) ((o) ^ (((o) >> 3) & 0x70))
#define NTILES (2 * (M_PAD / 128))   // 784

__global__ __launch_bounds__(256, 2) void gemm_mma_kernel(float* __restrict__ out) {
    __shared__ __align__(16) uint8_t sA[128 * 128];
    __shared__ __align__(16) uint8_t sB[128 * 128];
    __shared__ unsigned s_tile;

    const int tid  = threadIdx.x;
    const int lane = tid & 31;
    const int w    = tid >> 5;
    const int warpM = w & 3;
    const int warpN = w >> 2;

    const uint32_t sAu = smem_to_u32(sA);
    const uint32_t sBu = smem_to_u32(sB);

    const int aRow  = warpM * 32 + (lane & 15);
    const uint32_t aHalf = (uint32_t)((lane >> 4) << 4);
    const int bRowBase = warpN * 64 + (lane & 7) + (((lane >> 4) & 1) << 3);
    const uint32_t bHalf = (uint32_t)(((lane >> 3) & 1) << 4);
    const int groupID = lane >> 2;
    const int tig     = lane & 3;

    for (;;) {
        __syncthreads();
        if (tid == 0) s_tile = atomicAdd(&g_tile_ctr, 1u);
        __syncthreads();
        const unsigned t = s_tile;
        if (t >= NTILES) break;
        const int m0 = (int)(t >> 1) * 128;
        const int n0 = (int)(t & 1) * 128;

        float acc[2][8][4];
#pragma unroll
        for (int mi = 0; mi < 2; mi++)
#pragma unroll
            for (int nf = 0; nf < 8; nf++)
#pragma unroll
                for (int q = 0; q < 4; q++) acc[mi][nf][q] = 0.f;

#pragma unroll 1
        for (int it = 0; it < 12; ++it) {
            const int pass = it >> 2;
            const int k0   = (it & 3) * 64;
            const __nv_bfloat16* Ap = (pass < 2) ? g_hiA : g_loA;
            const __nv_bfloat16* Bp = (pass == 1) ? g_loB : g_hiB;

#pragma unroll
            for (int l = 0; l < 4; ++l) {
                int idx = tid + 256 * l;
                int row = idx >> 3;
                int u   = idx & 7;
                uint4 v = *reinterpret_cast<const uint4*>(
                              Ap + (size_t)(m0 + row) * IN_DIM + k0 + u * 8);
                *reinterpret_cast<uint4*>(sA + SWX(row * 128 + u * 16)) = v;
            }
#pragma unroll
            for (int l = 0; l < 4; ++l) {
                int idx = tid + 256 * l;
                int row = idx >> 3;
                int u   = idx & 7;
                uint4 v = *reinterpret_cast<const uint4*>(
                              Bp + (size_t)(n0 + row) * IN_DIM + k0 + u * 8);
                *reinterpret_cast<uint4*>(sB + SWX(row * 128 + u * 16)) = v;
            }
            __syncthreads();

#pragma unroll
            for (int ks = 0; ks < 4; ++ks) {
                const uint32_t koff = (uint32_t)(ks * 32);
                uint32_t afr[2][4];
#pragma unroll
                for (int mi = 0; mi < 2; mi++) {
                    const int r = aRow + mi * 16;
                    uint32_t addr = sAu + (uint32_t)(r * 128)
                                  + ((koff + aHalf) ^ ((uint32_t)((r << 4) & 0x70)));
                    ldm4(afr[mi], addr);
                }
#pragma unroll
                for (int nf2 = 0; nf2 < 4; nf2++) {
                    const int bRow = bRowBase + nf2 * 16;
                    uint32_t baddr = sBu + (uint32_t)(bRow * 128)
                                   + ((koff + bHalf) ^ ((uint32_t)((bRow << 4) & 0x70)));
                    uint32_t bfr[4];
                    ldm4(bfr, baddr);
#pragma unroll
                    for (int mi = 0; mi < 2; mi++) {
                        mma16816(acc[mi][nf2 * 2],     afr[mi], bfr[0], bfr[1]);
                        mma16816(acc[mi][nf2 * 2 + 1], afr[mi], bfr[2], bfr[3]);
                    }
                }
            }
            __syncthreads();
        }

        // epilogue
#pragma unroll
        for (int mi = 0; mi < 2; mi++) {
#pragma unroll
            for (int nf = 0; nf < 8; nf++) {
                int row0 = m0 + warpM * 32 + mi * 16 + groupID;
                int col  = n0 + warpN * 64 + nf * 8 + tig * 2;
                if (row0 < N_NODES) {
                    float2 v0 = make_float2(acc[mi][nf][0], acc[mi][nf][1]);
                    *reinterpret_cast<float2*>(out + (size_t)row0 * OUT_DIM + col) = v0;
                }
                int row1 = row0 + 8;
                if (row1 < N_NODES) {
                    float2 v1 = make_float2(acc[mi][nf][2], acc[mi][nf][3]);
                    *reinterpret_cast<float2*>(out + (size_t)row1 * OUT_DIM + col) = v1;
                }
            }
        }
    }
}

// ---------------------------------------------------------------------------
extern "C" void kernel_launch(void* const* d_in, const int* in_sizes, int n_in,
                              void* d_out, int out_size) {
    const float* feature = (const float*)d_in[0];
    const float* weight  = (const float*)d_in[1];
    const int*   src     = (const int*)d_in[2];
    const int*   dst     = (const int*)d_in[3];
    float*       out     = (float*)d_out;
    const int n_edges = in_sizes[2];

    convw_zero_kernel<<<(IN_DIM * OUT_DIM + 255) / 256, 256>>>(weight);
    hist_kernel<<<(n_edges + 255) / 256, 256>>>(dst, n_edges);
    convf_kernel<<<((N_NODES * IN_DIM / 8) + 255) / 256, 256>>>(feature);
    scan_a_kernel<<<SCAN_NB, SCAN_BLK>>>();
    scan_c_kernel<<<SCAN_NB, SCAN_BLK>>>();
    fill_kernel<<<(n_edges + 255) / 256, 256>>>(src, dst, n_edges);
    // gather: 2 warps per node
    gather_kernel<<<(2 * N_NODES * 32 + 255) / 256, 256>>>();
    gemm_mma_kernel<<<296, 256>>>(out);
}

// round 15
// speedup vs baseline: 1.9924x; 1.0708x over previous
#include <cuda_runtime.h>
#include <cuda_bf16.h>
#include <cuda_fp16.h>
#include <cstdint>

#define N_NODES 50000
#define N_EDGES_MAX 800000
#define IN_DIM  256
#define OUT_DIM 256
#define M_PAD   50176          // 392 * 128

// ---------------------------------------------------------------------------
// Device-global scratch (allocation-free).
// ---------------------------------------------------------------------------
__device__ int g_deg[N_NODES];
__device__ int g_off[N_NODES + 1];
__device__ int g_cur[N_NODES];
__device__ int g_esrc[N_EDGES_MAX];
#define SCAN_BLK 512
#define SCAN_NB  98            // 98*512 = 50176 >= N_NODES
__device__ int g_bsum[SCAN_NB];
__device__ unsigned g_tile_ctr;
// fp16 copy of feature (halves gather read traffic)
__device__ __align__(16) __half g_f16[(size_t)N_NODES * IN_DIM];
// fp16 aggregated features (A) and transposed weight (B)
// rows >= N_NODES are never written -> remain zero (device globals zero-init)
__device__ __align__(16) __half g_aggh[(size_t)M_PAD * IN_DIM];
__device__ __align__(16) __half g_hB[(size_t)OUT_DIM * IN_DIM];   // [n][k]

// ---------------------------------------------------------------------------
// helpers
// ---------------------------------------------------------------------------
__device__ __forceinline__ uint32_t smem_to_u32(const void* p) {
    uint32_t a;
    asm("{ .reg .u64 t; cvta.to.shared.u64 t, %1; cvt.u32.u64 %0, t; }"
        : "=r"(a) : "l"(p));
    return a;
}
__device__ __forceinline__ void ldm4(uint32_t* r, uint32_t addr) {
    asm volatile("ldmatrix.sync.aligned.m8n8.x4.shared.b16 {%0,%1,%2,%3}, [%4];"
                 : "=r"(r[0]), "=r"(r[1]), "=r"(r[2]), "=r"(r[3]) : "r"(addr));
}
__device__ __forceinline__ void mma16816h(float* c, const uint32_t* a,
                                          uint32_t b0, uint32_t b1) {
    asm volatile(
        "mma.sync.aligned.m16n8k16.row.col.f32.f16.f16.f32 "
        "{%0,%1,%2,%3}, {%4,%5,%6,%7}, {%8,%9}, {%0,%1,%2,%3};"
        : "+f"(c[0]), "+f"(c[1]), "+f"(c[2]), "+f"(c[3])
        : "r"(a[0]), "r"(a[1]), "r"(a[2]), "r"(a[3]), "r"(b0), "r"(b1));
}

// ---------------------------------------------------------------------------
// Kernel 1: convert W -> transposed fp16 plane (B[n][k] = W[k][n]),
// fused with: zero degree histogram + GEMM tile-ticket reset.
// ---------------------------------------------------------------------------
__global__ __launch_bounds__(256) void convw_zero_kernel(const float* __restrict__ W) {
    int idx = blockIdx.x * blockDim.x + threadIdx.x;   // 0..65535
    if (idx == 0) g_tile_ctr = 0;
    if (idx < N_NODES) g_deg[idx] = 0;
    if (idx >= IN_DIM * OUT_DIM) return;
    int k = idx >> 8;
    int n = idx & 255;
    g_hB[n * IN_DIM + k] = __float2half(W[idx]);
}

// ---------------------------------------------------------------------------
// Kernel 2 (FUSED): feature->fp16 conversion + degree histogram.
// convf: 1.6M threads (8 floats each); hist: first 800K threads.
// ---------------------------------------------------------------------------
__global__ __launch_bounds__(256) void convf_hist_kernel(const float* __restrict__ feature,
                                                         const int* __restrict__ dst,
                                                         int n_edges) {
    int i = blockIdx.x * blockDim.x + threadIdx.x;
    if (i < n_edges) atomicAdd(&g_deg[dst[i]], 1);
    const int n8 = (N_NODES * IN_DIM) / 8;
    if (i >= n8) return;
    float4 a = reinterpret_cast<const float4*>(feature)[2 * i];
    float4 b = reinterpret_cast<const float4*>(feature)[2 * i + 1];
    __half2 h0 = __floats2half2_rn(a.x, a.y);
    __half2 h1 = __floats2half2_rn(a.z, a.w);
    __half2 h2 = __floats2half2_rn(b.x, b.y);
    __half2 h3 = __floats2half2_rn(b.z, b.w);
    uint4 v;
    v.x = *reinterpret_cast<uint32_t*>(&h0);
    v.y = *reinterpret_cast<uint32_t*>(&h1);
    v.z = *reinterpret_cast<uint32_t*>(&h2);
    v.w = *reinterpret_cast<uint32_t*>(&h3);
    reinterpret_cast<uint4*>(g_f16)[i] = v;
}

// ---------------------------------------------------------------------------
// Kernels 3a/3c: parallel exclusive scan of degrees -> offsets + cursors
// ---------------------------------------------------------------------------
__global__ __launch_bounds__(SCAN_BLK) void scan_a_kernel() {
    __shared__ int sh[SCAN_BLK];
    int t = threadIdx.x;
    int i = blockIdx.x * SCAN_BLK + t;
    sh[t] = (i < N_NODES) ? g_deg[i] : 0;
    __syncthreads();
    for (int s = SCAN_BLK / 2; s > 0; s >>= 1) {
        if (t < s) sh[t] += sh[t + s];
        __syncthreads();
    }
    if (t == 0) g_bsum[blockIdx.x] = sh[0];
}

__global__ __launch_bounds__(SCAN_BLK) void scan_c_kernel() {
    __shared__ int sh[SCAN_BLK];
    __shared__ int s_bpre;
    int t = threadIdx.x;
    int i = blockIdx.x * SCAN_BLK + t;

    if (t < 128) {
        int v = (t < blockIdx.x && t < SCAN_NB) ? g_bsum[t] : 0;
        sh[t] = v;
    }
    __syncthreads();
    if (t < 64) sh[t] += sh[t + 64];
    __syncthreads();
    if (t < 32) {
        int v = sh[t] + sh[t + 32];
        for (int o = 16; o > 0; o >>= 1) v += __shfl_down_sync(0xFFFFFFFF, v, o);
        if (t == 0) s_bpre = v;
    }
    __syncthreads();
    const int bpre = s_bpre;
    __syncthreads();

    int v = (i < N_NODES) ? g_deg[i] : 0;
    sh[t] = v;
    __syncthreads();
    for (int d = 1; d < SCAN_BLK; d <<= 1) {
        int x = (t >= d) ? sh[t - d] : 0;
        __syncthreads();
        sh[t] += x;
        __syncthreads();
    }
    int off = bpre + sh[t] - v;
    if (i < N_NODES) {
        g_off[i] = off;
        g_cur[i] = off;
    }
    if (i == N_NODES - 1) g_off[N_NODES] = off + v;
}

// ---------------------------------------------------------------------------
// Kernel 4: fill CSR edge lists
// ---------------------------------------------------------------------------
__global__ void fill_kernel(const int* __restrict__ src,
                            const int* __restrict__ dst, int n_edges) {
    int e = blockIdx.x * blockDim.x + threadIdx.x;
    if (e < n_edges) {
        int d = dst[e];
        int p = atomicAdd(&g_cur[d], 1);
        g_esrc[p] = src[e];
    }
}

// ---------------------------------------------------------------------------
// Kernel 5: gather (fp16 features) -> fp16 agg plane.
// TWO warps per node (half row each), 1 uint2 (4 halves) per lane per edge,
// 4-edge unroll, f32 accumulation.
// ---------------------------------------------------------------------------
__device__ __forceinline__ void acch4(float* a, uint2 v) {
    __half2 h0 = *reinterpret_cast<__half2*>(&v.x);
    __half2 h1 = *reinterpret_cast<__half2*>(&v.y);
    float2 f0 = __half22float2(h0);
    float2 f1 = __half22float2(h1);
    a[0] += f0.x; a[1] += f0.y; a[2] += f1.x; a[3] += f1.y;
}

__global__ __launch_bounds__(256) void gather_kernel() {
    int gw   = (blockIdx.x * blockDim.x + threadIdx.x) >> 5;
    int node = gw >> 1;
    int half = gw & 1;
    int lane = threadIdx.x & 31;
    if (node >= N_NODES) return;

    int beg = g_off[node];
    int end = g_off[node + 1];

    const uint2* fbase = reinterpret_cast<const uint2*>(g_f16) + half * 32 + lane;

    float acc[4];
    acc[0] = acc[1] = acc[2] = acc[3] = 0.f;

    int i = beg;
    for (; i + 4 <= end; i += 4) {
        int s0 = g_esrc[i];
        int s1 = g_esrc[i + 1];
        int s2 = g_esrc[i + 2];
        int s3 = g_esrc[i + 3];
        uint2 v0 = fbase[(size_t)s0 * 64];
        uint2 v1 = fbase[(size_t)s1 * 64];
        uint2 v2 = fbase[(size_t)s2 * 64];
        uint2 v3 = fbase[(size_t)s3 * 64];
        acch4(acc, v0); acch4(acc, v1); acch4(acc, v2); acch4(acc, v3);
    }
    for (; i < end; ++i) {
        acch4(acc, fbase[(size_t)g_esrc[i] * 64]);
    }

    __half2 o0 = __floats2half2_rn(acc[0], acc[1]);
    __half2 o1 = __floats2half2_rn(acc[2], acc[3]);
    uint2 o;
    o.x = *reinterpret_cast<uint32_t*>(&o0);
    o.y = *reinterpret_cast<uint32_t*>(&o1);
    size_t base = (size_t)node * IN_DIM + half * 128;
    *reinterpret_cast<uint2*>(g_aggh + base + 4 * lane) = o;
}

// ---------------------------------------------------------------------------
// Kernel 6: fp16 HMMA GEMM (single pass), persistent CTAs with dynamic tile
// ticket. Tile 128x128, 8 warps (4M x 2N), K-chunk 64, 4 chunks total.
// ---------------------------------------------------------------------------
#define SWX(o) ((o) ^ (((o) >> 3) & 0x70))
#define NTILES (2 * (M_PAD / 128))   // 784

__global__ __launch_bounds__(256, 2) void gemm_mma_kernel(float* __restrict__ out) {
    __shared__ __align__(16) uint8_t sA[128 * 128];
    __shared__ __align__(16) uint8_t sB[128 * 128];
    __shared__ unsigned s_tile;

    const int tid  = threadIdx.x;
    const int lane = tid & 31;
    const int w    = tid >> 5;
    const int warpM = w & 3;
    const int warpN = w >> 2;

    const uint32_t sAu = smem_to_u32(sA);
    const uint32_t sBu = smem_to_u32(sB);

    const int aRow  = warpM * 32 + (lane & 15);
    const uint32_t aHalf = (uint32_t)((lane >> 4) << 4);
    const int bRowBase = warpN * 64 + (lane & 7) + (((lane >> 4) & 1) << 3);
    const uint32_t bHalf = (uint32_t)(((lane >> 3) & 1) << 4);
    const int groupID = lane >> 2;
    const int tig     = lane & 3;

    for (;;) {
        __syncthreads();
        if (tid == 0) s_tile = atomicAdd(&g_tile_ctr, 1u);
        __syncthreads();
        const unsigned t = s_tile;
        if (t >= NTILES) break;
        const int m0 = (int)(t >> 1) * 128;
        const int n0 = (int)(t & 1) * 128;

        float acc[2][8][4];
#pragma unroll
        for (int mi = 0; mi < 2; mi++)
#pragma unroll
            for (int nf = 0; nf < 8; nf++)
#pragma unroll
                for (int q = 0; q < 4; q++) acc[mi][nf][q] = 0.f;

#pragma unroll 1
        for (int it = 0; it < 4; ++it) {
            const int k0 = it * 64;

#pragma unroll
            for (int l = 0; l < 4; ++l) {
                int idx = tid + 256 * l;
                int row = idx >> 3;
                int u   = idx & 7;
                uint4 v = *reinterpret_cast<const uint4*>(
                              g_aggh + (size_t)(m0 + row) * IN_DIM + k0 + u * 8);
                *reinterpret_cast<uint4*>(sA + SWX(row * 128 + u * 16)) = v;
            }
#pragma unroll
            for (int l = 0; l < 4; ++l) {
                int idx = tid + 256 * l;
                int row = idx >> 3;
                int u   = idx & 7;
                uint4 v = *reinterpret_cast<const uint4*>(
                              g_hB + (size_t)(n0 + row) * IN_DIM + k0 + u * 8);
                *reinterpret_cast<uint4*>(sB + SWX(row * 128 + u * 16)) = v;
            }
            __syncthreads();

#pragma unroll
            for (int ks = 0; ks < 4; ++ks) {
                const uint32_t koff = (uint32_t)(ks * 32);
                uint32_t afr[2][4];
#pragma unroll
                for (int mi = 0; mi < 2; mi++) {
                    const int r = aRow + mi * 16;
                    uint32_t addr = sAu + (uint32_t)(r * 128)
                                  + ((koff + aHalf) ^ ((uint32_t)((r << 4) & 0x70)));
                    ldm4(afr[mi], addr);
                }
#pragma unroll
                for (int nf2 = 0; nf2 < 4; nf2++) {
                    const int bRow = bRowBase + nf2 * 16;
                    uint32_t baddr = sBu + (uint32_t)(bRow * 128)
                                   + ((koff + bHalf) ^ ((uint32_t)((bRow << 4) & 0x70)));
                    uint32_t bfr[4];
                    ldm4(bfr, baddr);
#pragma unroll
                    for (int mi = 0; mi < 2; mi++) {
                        mma16816h(acc[mi][nf2 * 2],     afr[mi], bfr[0], bfr[1]);
                        mma16816h(acc[mi][nf2 * 2 + 1], afr[mi], bfr[2], bfr[3]);
                    }
                }
            }
            __syncthreads();
        }

        // epilogue
#pragma unroll
        for (int mi = 0; mi < 2; mi++) {
#pragma unroll
            for (int nf = 0; nf < 8; nf++) {
                int row0 = m0 + warpM * 32 + mi * 16 + groupID;
                int col  = n0 + warpN * 64 + nf * 8 + tig * 2;
                if (row0 < N_NODES) {
                    float2 v0 = make_float2(acc[mi][nf][0], acc[mi][nf][1]);
                    *reinterpret_cast<float2*>(out + (size_t)row0 * OUT_DIM + col) = v0;
                }
                int row1 = row0 + 8;
                if (row1 < N_NODES) {
                    float2 v1 = make_float2(acc[mi][nf][2], acc[mi][nf][3]);
                    *reinterpret_cast<float2*>(out + (size_t)row1 * OUT_DIM + col) = v1;
                }
            }
        }
    }
}

// ---------------------------------------------------------------------------
extern "C" void kernel_launch(void* const* d_in, const int* in_sizes, int n_in,
                              void* d_out, int out_size) {
    const float* feature = (const float*)d_in[0];
    const float* weight  = (const float*)d_in[1];
    const int*   src     = (const int*)d_in[2];
    const int*   dst     = (const int*)d_in[3];
    float*       out     = (float*)d_out;
    const int n_edges = in_sizes[2];

    convw_zero_kernel<<<(IN_DIM * OUT_DIM + 255) / 256, 256>>>(weight);
    convf_hist_kernel<<<((N_NODES * IN_DIM / 8) + 255) / 256, 256>>>(feature, dst, n_edges);
    scan_a_kernel<<<SCAN_NB, SCAN_BLK>>>();
    scan_c_kernel<<<SCAN_NB, SCAN_BLK>>>();
    fill_kernel<<<(n_edges + 255) / 256, 256>>>(src, dst, n_edges);
    // gather: 2 warps per node
    gather_kernel<<<(2 * N_NODES * 32 + 255) / 256, 256>>>();
    gemm_mma_kernel<<<296, 256>>>(out);
}

// round 16
// speedup vs baseline: 2.7485x; 1.3795x over previous
#include <cuda_runtime.h>
#include <cuda_bf16.h>
#include <cuda_fp16.h>
#include <cstdint>

#define N_NODES 50000
#define N_EDGES_MAX 800000
#define IN_DIM  256
#define OUT_DIM 256
#define M_PAD   50176          // 392 * 128

// ---------------------------------------------------------------------------
// Device-global scratch (allocation-free).
// ---------------------------------------------------------------------------
__device__ int g_deg[N_NODES];
__device__ int g_off[N_NODES + 1];
__device__ int g_cur[N_NODES];
__device__ int g_esrc[N_EDGES_MAX];
#define PRE_BLK 512
#define PRE_NB  98             // 98*512 = 50176 >= N_NODES; 98 < 148 SMs
__device__ int g_bsum[PRE_NB];
__device__ unsigned g_tile_ctr;
__device__ unsigned g_bar;
// fp16 copy of feature (halves gather read traffic)
__device__ __align__(16) __half g_f16[(size_t)N_NODES * IN_DIM];
// fp16 aggregated features (A) and transposed weight (B)
// rows >= N_NODES are never written -> remain zero (device globals zero-init)
__device__ __align__(16) __half g_aggh[(size_t)M_PAD * IN_DIM];
__device__ __align__(16) __half g_hB[(size_t)OUT_DIM * IN_DIM];   // [n][k]

// ---------------------------------------------------------------------------
// helpers
// ---------------------------------------------------------------------------
__device__ __forceinline__ uint32_t smem_to_u32(const void* p) {
    uint32_t a;
    asm("{ .reg .u64 t; cvta.to.shared.u64 t, %1; cvt.u32.u64 %0, t; }"
        : "=r"(a) : "l"(p));
    return a;
}
__device__ __forceinline__ void ldm4(uint32_t* r, uint32_t addr) {
    asm volatile("ldmatrix.sync.aligned.m8n8.x4.shared.b16 {%0,%1,%2,%3}, [%4];"
                 : "=r"(r[0]), "=r"(r[1]), "=r"(r[2]), "=r"(r[3]) : "r"(addr));
}
__device__ __forceinline__ void mma16816h(float* c, const uint32_t* a,
                                          uint32_t b0, uint32_t b1) {
    asm volatile(
        "mma.sync.aligned.m16n8k16.row.col.f32.f16.f16.f32 "
        "{%0,%1,%2,%3}, {%4,%5,%6,%7}, {%8,%9}, {%0,%1,%2,%3};"
        : "+f"(c[0]), "+f"(c[1]), "+f"(c[2]), "+f"(c[3])
        : "r"(a[0]), "r"(a[1]), "r"(a[2]), "r"(a[3]), "r"(b0), "r"(b1));
}

// ---------------------------------------------------------------------------
// Kernel 1: convert W -> transposed fp16 plane (B[n][k] = W[k][n]),
// fused with: zero degree histogram + ticket/barrier reset.
// ---------------------------------------------------------------------------
__global__ __launch_bounds__(256) void convw_zero_kernel(const float* __restrict__ W) {
    int idx = blockIdx.x * blockDim.x + threadIdx.x;   // 0..65535
    if (idx == 0) { g_tile_ctr = 0; g_bar = 0; }
    if (idx < N_NODES) g_deg[idx] = 0;
    if (idx >= IN_DIM * OUT_DIM) return;
    int k = idx >> 8;
    int n = idx & 255;
    g_hB[n * IN_DIM + k] = __float2half(W[idx]);
}

// ---------------------------------------------------------------------------
// Kernel 2 (FUSED): feature->fp16 conversion + degree histogram.
// ---------------------------------------------------------------------------
__global__ __launch_bounds__(256) void convf_hist_kernel(const float* __restrict__ feature,
                                                         const int* __restrict__ dst,
                                                         int n_edges) {
    int i = blockIdx.x * blockDim.x + threadIdx.x;
    if (i < n_edges) atomicAdd(&g_deg[dst[i]], 1);
    const int n8 = (N_NODES * IN_DIM) / 8;
    if (i >= n8) return;
    float4 a = reinterpret_cast<const float4*>(feature)[2 * i];
    float4 b = reinterpret_cast<const float4*>(feature)[2 * i + 1];
    __half2 h0 = __floats2half2_rn(a.x, a.y);
    __half2 h1 = __floats2half2_rn(a.z, a.w);
    __half2 h2 = __floats2half2_rn(b.x, b.y);
    __half2 h3 = __floats2half2_rn(b.z, b.w);
    uint4 v;
    v.x = *reinterpret_cast<uint32_t*>(&h0);
    v.y = *reinterpret_cast<uint32_t*>(&h1);
    v.z = *reinterpret_cast<uint32_t*>(&h2);
    v.w = *reinterpret_cast<uint32_t*>(&h3);
    reinterpret_cast<uint4*>(g_f16)[i] = v;
}

// ---------------------------------------------------------------------------
// Kernel 3 (FUSED, grid-resident): scan of degrees -> offsets + CSR fill.
// 98 CTAs x 512 threads: all co-resident (98 < 148 SMs) -> spin grid
// barriers are deadlock-free. Phases: intra-block scan -> barrier ->
// block-prefix + offsets -> barrier -> fill.
// ---------------------------------------------------------------------------
__device__ __forceinline__ void grid_barrier(unsigned target) {
    __threadfence();
    __syncthreads();
    if (threadIdx.x == 0) {
        atomicAdd(&g_bar, 1u);
        while (*((volatile unsigned*)&g_bar) < target) { }
    }
    __syncthreads();
}

__global__ __launch_bounds__(PRE_BLK) void scanfill_kernel(const int* __restrict__ src,
                                                           const int* __restrict__ dst,
                                                           int n_edges) {
    __shared__ int s_w[16];
    __shared__ int s_bpre;
    const int t = threadIdx.x;
    const int b = blockIdx.x;
    const int i = b * PRE_BLK + t;
    const int lane = t & 31;
    const int wid  = t >> 5;

    // --- intra-block inclusive scan of degrees (warp shuffle) ---
    int v = (i < N_NODES) ? g_deg[i] : 0;
    int x = v;
#pragma unroll
    for (int o = 1; o < 32; o <<= 1) {
        int y = __shfl_up_sync(0xFFFFFFFFu, x, o);
        if (lane >= o) x += y;
    }
    if (lane == 31) s_w[wid] = x;
    __syncthreads();
    if (wid == 0) {
        int y = (lane < 16) ? s_w[lane] : 0;
#pragma unroll
        for (int o = 1; o < 16; o <<= 1) {
            int z = __shfl_up_sync(0xFFFFFFFFu, y, o);
            if (lane >= o) y += z;
        }
        if (lane < 16) s_w[lane] = y;
    }
    __syncthreads();
    const int incl = x + (wid ? s_w[wid - 1] : 0);
    if (t == PRE_BLK - 1) g_bsum[b] = incl;           // block total
    __syncthreads();                                   // s_w reads done

    // --- grid barrier 1: all block totals visible ---
    grid_barrier(PRE_NB);

    // --- block prefix: sum of g_bsum[0..b) (first 128 threads) ---
    if (t < 128) {
        int bv = (t < b) ? __ldcg(&g_bsum[t]) : 0;
#pragma unroll
        for (int o = 16; o > 0; o >>= 1) bv += __shfl_down_sync(0xFFFFFFFFu, bv, o);
        if (lane == 0) s_w[wid] = bv;
    }
    __syncthreads();
    if (t == 0) s_bpre = s_w[0] + s_w[1] + s_w[2] + s_w[3];
    __syncthreads();

    const int off = s_bpre + incl - v;                 // exclusive global prefix
    if (i < N_NODES) {
        g_off[i] = off;
        g_cur[i] = off;
    }
    if (i == N_NODES - 1) g_off[N_NODES] = off + v;

    // --- grid barrier 2: all offsets/cursors visible ---
    grid_barrier(2 * PRE_NB);

    // --- fill CSR edge lists (grid-strided) ---
    const int stride = PRE_NB * PRE_BLK;
    for (int e = b * PRE_BLK + t; e < n_edges; e += stride) {
        int d = dst[e];
        int p = atomicAdd(&g_cur[d], 1);
        g_esrc[p] = src[e];
    }
}

// ---------------------------------------------------------------------------
// Kernel 4: gather (fp16 features) -> fp16 agg plane.
// TWO warps per node (half row each), 1 uint2 (4 halves) per lane per edge,
// 4-edge unroll, f32 accumulation.
// ---------------------------------------------------------------------------
__device__ __forceinline__ void acch4(float* a, uint2 v) {
    __half2 h0 = *reinterpret_cast<__half2*>(&v.x);
    __half2 h1 = *reinterpret_cast<__half2*>(&v.y);
    float2 f0 = __half22float2(h0);
    float2 f1 = __half22float2(h1);
    a[0] += f0.x; a[1] += f0.y; a[2] += f1.x; a[3] += f1.y;
}

__global__ __launch_bounds__(256) void gather_kernel() {
    int gw   = (blockIdx.x * blockDim.x + threadIdx.x) >> 5;
    int node = gw >> 1;
    int half = gw & 1;
    int lane = threadIdx.x & 31;
    if (node >= N_NODES) return;

    int beg = g_off[node];
    int end = g_off[node + 1];

    const uint2* fbase = reinterpret_cast<const uint2*>(g_f16) + half * 32 + lane;

    float acc[4];
    acc[0] = acc[1] = acc[2] = acc[3] = 0.f;

    int i = beg;
    for (; i + 4 <= end; i += 4) {
        int s0 = g_esrc[i];
        int s1 = g_esrc[i + 1];
        int s2 = g_esrc[i + 2];
        int s3 = g_esrc[i + 3];
        uint2 v0 = fbase[(size_t)s0 * 64];
        uint2 v1 = fbase[(size_t)s1 * 64];
        uint2 v2 = fbase[(size_t)s2 * 64];
        uint2 v3 = fbase[(size_t)s3 * 64];
        acch4(acc, v0); acch4(acc, v1); acch4(acc, v2); acch4(acc, v3);
    }
    for (; i < end; ++i) {
        acch4(acc, fbase[(size_t)g_esrc[i] * 64]);
    }

    __half2 o0 = __floats2half2_rn(acc[0], acc[1]);
    __half2 o1 = __floats2half2_rn(acc[2], acc[3]);
    uint2 o;
    o.x = *reinterpret_cast<uint32_t*>(&o0);
    o.y = *reinterpret_cast<uint32_t*>(&o1);
    size_t base = (size_t)node * IN_DIM + half * 128;
    *reinterpret_cast<uint2*>(g_aggh + base + 4 * lane) = o;
}

// ---------------------------------------------------------------------------
// Kernel 5: fp16 HMMA GEMM (single pass), persistent CTAs with dynamic tile
// ticket. Tile 128x128, 8 warps (4M x 2N), K-chunk 64, 4 chunks total.
// ---------------------------------------------------------------------------
#define SWX(o) ((o) ^ (((o) >> 3) & 0x70))
#define NTILES (2 * (M_PAD / 128))   // 784

__global__ __launch_bounds__(256, 2) void gemm_mma_kernel(float* __restrict__ out) {
    __shared__ __align__(16) uint8_t sA[128 * 128];
    __shared__ __align__(16) uint8_t sB[128 * 128];
    __shared__ unsigned s_tile;

    const int tid  = threadIdx.x;
    const int lane = tid & 31;
    const int w    = tid >> 5;
    const int warpM = w & 3;
    const int warpN = w >> 2;

    const uint32_t sAu = smem_to_u32(sA);
    const uint32_t sBu = smem_to_u32(sB);

    const int aRow  = warpM * 32 + (lane & 15);
    const uint32_t aHalf = (uint32_t)((lane >> 4) << 4);
    const int bRowBase = warpN * 64 + (lane & 7) + (((lane >> 4) & 1) << 3);
    const uint32_t bHalf = (uint32_t)(((lane >> 3) & 1) << 4);
    const int groupID = lane >> 2;
    const int tig     = lane & 3;

    for (;;) {
        __syncthreads();
        if (tid == 0) s_tile = atomicAdd(&g_tile_ctr, 1u);
        __syncthreads();
        const unsigned t = s_tile;
        if (t >= NTILES) break;
        const int m0 = (int)(t >> 1) * 128;
        const int n0 = (int)(t & 1) * 128;

        float acc[2][8][4];
#pragma unroll
        for (int mi = 0; mi < 2; mi++)
#pragma unroll
            for (int nf = 0; nf < 8; nf++)
#pragma unroll
                for (int q = 0; q < 4; q++) acc[mi][nf][q] = 0.f;

#pragma unroll 1
        for (int it = 0; it < 4; ++it) {
            const int k0 = it * 64;

#pragma unroll
            for (int l = 0; l < 4; ++l) {
                int idx = tid + 256 * l;
                int row = idx >> 3;
                int u   = idx & 7;
                uint4 v = *reinterpret_cast<const uint4*>(
                              g_aggh + (size_t)(m0 + row) * IN_DIM + k0 + u * 8);
                *reinterpret_cast<uint4*>(sA + SWX(row * 128 + u * 16)) = v;
            }
#pragma unroll
            for (int l = 0; l < 4; ++l) {
                int idx = tid + 256 * l;
                int row = idx >> 3;
                int u   = idx & 7;
                uint4 v = *reinterpret_cast<const uint4*>(
                              g_hB + (size_t)(n0 + row) * IN_DIM + k0 + u * 8);
                *reinterpret_cast<uint4*>(sB + SWX(row * 128 + u * 16)) = v;
            }
            __syncthreads();

#pragma unroll
            for (int ks = 0; ks < 4; ++ks) {
                const uint32_t koff = (uint32_t)(ks * 32);
                uint32_t afr[2][4];
#pragma unroll
                for (int mi = 0; mi < 2; mi++) {
                    const int r = aRow + mi * 16;
                    uint32_t addr = sAu + (uint32_t)(r * 128)
                                  + ((koff + aHalf) ^ ((uint32_t)((r << 4) & 0x70)));
                    ldm4(afr[mi], addr);
                }
#pragma unroll
                for (int nf2 = 0; nf2 < 4; nf2++) {
                    const int bRow = bRowBase + nf2 * 16;
                    uint32_t baddr = sBu + (uint32_t)(bRow * 128)
                                   + ((koff + bHalf) ^ ((uint32_t)((bRow << 4) & 0x70)));
                    uint32_t bfr[4];
                    ldm4(bfr, baddr);
#pragma unroll
                    for (int mi = 0; mi < 2; mi++) {
                        mma16816h(acc[mi][nf2 * 2],     afr[mi], bfr[0], bfr[1]);
                        mma16816h(acc[mi][nf2 * 2 + 1], afr[mi], bfr[2], bfr[3]);
                    }
                }
            }
            __syncthreads();
        }

        // epilogue
#pragma unroll
        for (int mi = 0; mi < 2; mi++) {
#pragma unroll
            for (int nf = 0; nf < 8; nf++) {
                int row0 = m0 + warpM * 32 + mi * 16 + groupID;
                int col  = n0 + warpN * 64 + nf * 8 + tig * 2;
                if (row0 < N_NODES) {
                    float2 v0 = make_float2(acc[mi][nf][0], acc[mi][nf][1]);
                    *reinterpret_cast<float2*>(out + (size_t)row0 * OUT_DIM + col) = v0;
                }
                int row1 = row0 + 8;
                if (row1 < N_NODES) {
                    float2 v1 = make_float2(acc[mi][nf][2], acc[mi][nf][3]);
                    *reinterpret_cast<float2*>(out + (size_t)row1 * OUT_DIM + col) = v1;
                }
            }
        }
    }
}

// ---------------------------------------------------------------------------
extern "C" void kernel_launch(void* const* d_in, const int* in_sizes, int n_in,
                              void* d_out, int out_size) {
    const float* feature = (const float*)d_in[0];
    const float* weight  = (const float*)d_in[1];
    const int*   src     = (const int*)d_in[2];
    const int*   dst     = (const int*)d_in[3];
    float*       out     = (float*)d_out;
    const int n_edges = in_sizes[2];

    convw_zero_kernel<<<(IN_DIM * OUT_DIM + 255) / 256, 256>>>(weight);
    convf_hist_kernel<<<((N_NODES * IN_DIM / 8) + 255) / 256, 256>>>(feature, dst, n_edges);
    scanfill_kernel<<<PRE_NB, PRE_BLK>>>(src, dst, n_edges);
    // gather: 2 warps per node
    gather_kernel<<<(2 * N_NODES * 32 + 255) / 256, 256>>>();
    gemm_mma_kernel<<<296, 256>>>(out);
}

// round 17
// speedup vs baseline: 2.7895x; 1.0149x over previous
#include <cuda_runtime.h>
#include <cuda_bf16.h>
#include <cuda_fp16.h>
#include <cstdint>

#define N_NODES 50000
#define N_EDGES_MAX 800000
#define IN_DIM  256
#define OUT_DIM 256
#define M_PAD   50176          // 392 * 128

// ---------------------------------------------------------------------------
// Device-global scratch (allocation-free).
// ---------------------------------------------------------------------------
__device__ int g_deg[N_NODES];
__device__ int g_off[N_NODES + 1];
__device__ int g_cur[N_NODES];
__device__ int g_esrc[N_EDGES_MAX];
#define PRE_BLK 512
#define PRE_NB  98             // 98*512 = 50176 >= N_NODES; 98 < 148 SMs
__device__ int g_bsum[PRE_NB];
__device__ unsigned g_tile_ctr;
__device__ unsigned g_bar;
// fp16 copy of feature (halves gather read traffic)
__device__ __align__(16) __half g_f16[(size_t)N_NODES * IN_DIM];
// fp16 aggregated features (A) and transposed weight (B)
// rows >= N_NODES are never written -> remain zero (device globals zero-init)
__device__ __align__(16) __half g_aggh[(size_t)M_PAD * IN_DIM];
__device__ __align__(16) __half g_hB[(size_t)OUT_DIM * IN_DIM];   // [n][k]

// ---------------------------------------------------------------------------
// helpers
// ---------------------------------------------------------------------------
__device__ __forceinline__ uint32_t smem_to_u32(const void* p) {
    uint32_t a;
    asm("{ .reg .u64 t; cvta.to.shared.u64 t, %1; cvt.u32.u64 %0, t; }"
        : "=r"(a) : "l"(p));
    return a;
}
__device__ __forceinline__ void ldm4(uint32_t* r, uint32_t addr) {
    asm volatile("ldmatrix.sync.aligned.m8n8.x4.shared.b16 {%0,%1,%2,%3}, [%4];"
                 : "=r"(r[0]), "=r"(r[1]), "=r"(r[2]), "=r"(r[3]) : "r"(addr));
}
__device__ __forceinline__ void mma16816h(float* c, const uint32_t* a,
                                          uint32_t b0, uint32_t b1) {
    asm volatile(
        "mma.sync.aligned.m16n8k16.row.col.f32.f16.f16.f32 "
        "{%0,%1,%2,%3}, {%4,%5,%6,%7}, {%8,%9}, {%0,%1,%2,%3};"
        : "+f"(c[0]), "+f"(c[1]), "+f"(c[2]), "+f"(c[3])
        : "r"(a[0]), "r"(a[1]), "r"(a[2]), "r"(a[3]), "r"(b0), "r"(b1));
}

// ---------------------------------------------------------------------------
// Kernel 1: convert W -> transposed fp16 plane (B[n][k] = W[k][n]),
// fused with: zero degree histogram + ticket/barrier reset.
// ---------------------------------------------------------------------------
__global__ __launch_bounds__(256) void convw_zero_kernel(const float* __restrict__ W) {
    int idx = blockIdx.x * blockDim.x + threadIdx.x;   // 0..65535
    if (idx == 0) { g_tile_ctr = 0; g_bar = 0; }
    if (idx < N_NODES) g_deg[idx] = 0;
    if (idx >= IN_DIM * OUT_DIM) return;
    int k = idx >> 8;
    int n = idx & 255;
    g_hB[n * IN_DIM + k] = __float2half(W[idx]);
}

// ---------------------------------------------------------------------------
// Kernel 2 (FUSED): feature->fp16 conversion + degree histogram.
// ---------------------------------------------------------------------------
__global__ __launch_bounds__(256) void convf_hist_kernel(const float* __restrict__ feature,
                                                         const int* __restrict__ dst,
                                                         int n_edges) {
    int i = blockIdx.x * blockDim.x + threadIdx.x;
    if (i < n_edges) atomicAdd(&g_deg[dst[i]], 1);
    const int n8 = (N_NODES * IN_DIM) / 8;
    if (i >= n8) return;
    float4 a = reinterpret_cast<const float4*>(feature)[2 * i];
    float4 b = reinterpret_cast<const float4*>(feature)[2 * i + 1];
    __half2 h0 = __floats2half2_rn(a.x, a.y);
    __half2 h1 = __floats2half2_rn(a.z, a.w);
    __half2 h2 = __floats2half2_rn(b.x, b.y);
    __half2 h3 = __floats2half2_rn(b.z, b.w);
    uint4 v;
    v.x = *reinterpret_cast<uint32_t*>(&h0);
    v.y = *reinterpret_cast<uint32_t*>(&h1);
    v.z = *reinterpret_cast<uint32_t*>(&h2);
    v.w = *reinterpret_cast<uint32_t*>(&h3);
    reinterpret_cast<uint4*>(g_f16)[i] = v;
}

// ---------------------------------------------------------------------------
// Kernel 3 (FUSED, grid-resident): scan of degrees -> offsets + CSR fill.
// ---------------------------------------------------------------------------
__device__ __forceinline__ void grid_barrier(unsigned target) {
    __threadfence();
    __syncthreads();
    if (threadIdx.x == 0) {
        atomicAdd(&g_bar, 1u);
        while (*((volatile unsigned*)&g_bar) < target) { }
    }
    __syncthreads();
}

__global__ __launch_bounds__(PRE_BLK) void scanfill_kernel(const int* __restrict__ src,
                                                           const int* __restrict__ dst,
                                                           int n_edges) {
    __shared__ int s_w[16];
    __shared__ int s_bpre;
    const int t = threadIdx.x;
    const int b = blockIdx.x;
    const int i = b * PRE_BLK + t;
    const int lane = t & 31;
    const int wid  = t >> 5;

    // --- intra-block inclusive scan of degrees (warp shuffle) ---
    int v = (i < N_NODES) ? g_deg[i] : 0;
    int x = v;
#pragma unroll
    for (int o = 1; o < 32; o <<= 1) {
        int y = __shfl_up_sync(0xFFFFFFFFu, x, o);
        if (lane >= o) x += y;
    }
    if (lane == 31) s_w[wid] = x;
    __syncthreads();
    if (wid == 0) {
        int y = (lane < 16) ? s_w[lane] : 0;
#pragma unroll
        for (int o = 1; o < 16; o <<= 1) {
            int z = __shfl_up_sync(0xFFFFFFFFu, y, o);
            if (lane >= o) y += z;
        }
        if (lane < 16) s_w[lane] = y;
    }
    __syncthreads();
    const int incl = x + (wid ? s_w[wid - 1] : 0);
    if (t == PRE_BLK - 1) g_bsum[b] = incl;           // block total
    __syncthreads();                                   // s_w reads done

    // --- grid barrier 1: all block totals visible ---
    grid_barrier(PRE_NB);

    // --- block prefix: sum of g_bsum[0..b) (first 128 threads) ---
    if (t < 128) {
        int bv = (t < b) ? __ldcg(&g_bsum[t]) : 0;
#pragma unroll
        for (int o = 16; o > 0; o >>= 1) bv += __shfl_down_sync(0xFFFFFFFFu, bv, o);
        if (lane == 0) s_w[wid] = bv;
    }
    __syncthreads();
    if (t == 0) s_bpre = s_w[0] + s_w[1] + s_w[2] + s_w[3];
    __syncthreads();

    const int off = s_bpre + incl - v;                 // exclusive global prefix
    if (i < N_NODES) {
        g_off[i] = off;
        g_cur[i] = off;
    }
    if (i == N_NODES - 1) g_off[N_NODES] = off + v;

    // --- grid barrier 2: all offsets/cursors visible ---
    grid_barrier(2 * PRE_NB);

    // --- fill CSR edge lists (grid-strided) ---
    const int stride = PRE_NB * PRE_BLK;
    for (int e = b * PRE_BLK + t; e < n_edges; e += stride) {
        int d = dst[e];
        int p = atomicAdd(&g_cur[d], 1);
        g_esrc[p] = src[e];
    }
}

// ---------------------------------------------------------------------------
// Kernel 4: gather (fp16 features) -> fp16 agg plane.
// TWO warps per node (half row each), 1 uint2 (4 halves) per lane per edge.
// 4-edge batches: fp16 HADD2 tree (6 HADD2) -> one cvt+FADD carry into the
// fp32 master accumulator. Cuts warp-instructions/edge ~14 -> ~8.
// ---------------------------------------------------------------------------
__device__ __forceinline__ __half2 h2of(uint32_t u) {
    return *reinterpret_cast<__half2*>(&u);
}

__global__ __launch_bounds__(256) void gather_kernel() {
    int gw   = (blockIdx.x * blockDim.x + threadIdx.x) >> 5;
    int node = gw >> 1;
    int half = gw & 1;
    int lane = threadIdx.x & 31;
    if (node >= N_NODES) return;

    int beg = g_off[node];
    int end = g_off[node + 1];

    const uint2* fbase = reinterpret_cast<const uint2*>(g_f16) + half * 32 + lane;

    float acc[4];
    acc[0] = acc[1] = acc[2] = acc[3] = 0.f;

    int i = beg;
    for (; i + 4 <= end; i += 4) {
        int s0 = g_esrc[i];
        int s1 = g_esrc[i + 1];
        int s2 = g_esrc[i + 2];
        int s3 = g_esrc[i + 3];
        uint2 v0 = fbase[(size_t)s0 * 64];
        uint2 v1 = fbase[(size_t)s1 * 64];
        uint2 v2 = fbase[(size_t)s2 * 64];
        uint2 v3 = fbase[(size_t)s3 * 64];
        // fp16 tree-sum of the 4 edges, then fp32 carry
        __half2 sx = __hadd2(__hadd2(h2of(v0.x), h2of(v1.x)),
                             __hadd2(h2of(v2.x), h2of(v3.x)));
        __half2 sy = __hadd2(__hadd2(h2of(v0.y), h2of(v1.y)),
                             __hadd2(h2of(v2.y), h2of(v3.y)));
        float2 f0 = __half22float2(sx);
        float2 f1 = __half22float2(sy);
        acc[0] += f0.x; acc[1] += f0.y; acc[2] += f1.x; acc[3] += f1.y;
    }
    for (; i < end; ++i) {
        uint2 v = fbase[(size_t)g_esrc[i] * 64];
        float2 f0 = __half22float2(h2of(v.x));
        float2 f1 = __half22float2(h2of(v.y));
        acc[0] += f0.x; acc[1] += f0.y; acc[2] += f1.x; acc[3] += f1.y;
    }

    __half2 o0 = __floats2half2_rn(acc[0], acc[1]);
    __half2 o1 = __floats2half2_rn(acc[2], acc[3]);
    uint2 o;
    o.x = *reinterpret_cast<uint32_t*>(&o0);
    o.y = *reinterpret_cast<uint32_t*>(&o1);
    size_t base = (size_t)node * IN_DIM + half * 128;
    *reinterpret_cast<uint2*>(g_aggh + base + 4 * lane) = o;
}

// ---------------------------------------------------------------------------
// Kernel 5: fp16 HMMA GEMM (single pass), persistent CTAs with dynamic tile
// ticket. Tile 128x128, 8 warps (4M x 2N), K-chunk 64, 4 chunks total.
// ---------------------------------------------------------------------------
#define SWX(o) ((o) ^ (((o) >> 3) & 0x70))
#define NTILES (2 * (M_PAD / 128))   // 784

__global__ __launch_bounds__(256, 2) void gemm_mma_kernel(float* __restrict__ out) {
    __shared__ __align__(16) uint8_t sA[128 * 128];
    __shared__ __align__(16) uint8_t sB[128 * 128];
    __shared__ unsigned s_tile;

    const int tid  = threadIdx.x;
    const int lane = tid & 31;
    const int w    = tid >> 5;
    const int warpM = w & 3;
    const int warpN = w >> 2;

    const uint32_t sAu = smem_to_u32(sA);
    const uint32_t sBu = smem_to_u32(sB);

    const int aRow  = warpM * 32 + (lane & 15);
    const uint32_t aHalf = (uint32_t)((lane >> 4) << 4);
    const int bRowBase = warpN * 64 + (lane & 7) + (((lane >> 4) & 1) << 3);
    const uint32_t bHalf = (uint32_t)(((lane >> 3) & 1) << 4);
    const int groupID = lane >> 2;
    const int tig     = lane & 3;

    for (;;) {
        __syncthreads();
        if (tid == 0) s_tile = atomicAdd(&g_tile_ctr, 1u);
        __syncthreads();
        const unsigned t = s_tile;
        if (t >= NTILES) break;
        const int m0 = (int)(t >> 1) * 128;
        const int n0 = (int)(t & 1) * 128;

        float acc[2][8][4];
#pragma unroll
        for (int mi = 0; mi < 2; mi++)
#pragma unroll
            for (int nf = 0; nf < 8; nf++)
#pragma unroll
                for (int q = 0; q < 4; q++) acc[mi][nf][q] = 0.f;

#pragma unroll 1
        for (int it = 0; it < 4; ++it) {
            const int k0 = it * 64;

#pragma unroll
            for (int l = 0; l < 4; ++l) {
                int idx = tid + 256 * l;
                int row = idx >> 3;
                int u   = idx & 7;
                uint4 v = *reinterpret_cast<const uint4*>(
                              g_aggh + (size_t)(m0 + row) * IN_DIM + k0 + u * 8);
                *reinterpret_cast<uint4*>(sA + SWX(row * 128 + u * 16)) = v;
            }
#pragma unroll
            for (int l = 0; l < 4; ++l) {
                int idx = tid + 256 * l;
                int row = idx >> 3;
                int u   = idx & 7;
                uint4 v = *reinterpret_cast<const uint4*>(
                              g_hB + (size_t)(n0 + row) * IN_DIM + k0 + u * 8);
                *reinterpret_cast<uint4*>(sB + SWX(row * 128 + u * 16)) = v;
            }
            __syncthreads();

#pragma unroll
            for (int ks = 0; ks < 4; ++ks) {
                const uint32_t koff = (uint32_t)(ks * 32);
                uint32_t afr[2][4];
#pragma unroll
                for (int mi = 0; mi < 2; mi++) {
                    const int r = aRow + mi * 16;
                    uint32_t addr = sAu + (uint32_t)(r * 128)
                                  + ((koff + aHalf) ^ ((uint32_t)((r << 4) & 0x70)));
                    ldm4(afr[mi], addr);
                }
#pragma unroll
                for (int nf2 = 0; nf2 < 4; nf2++) {
                    const int bRow = bRowBase + nf2 * 16;
                    uint32_t baddr = sBu + (uint32_t)(bRow * 128)
                                   + ((koff + bHalf) ^ ((uint32_t)((bRow << 4) & 0x70)));
                    uint32_t bfr[4];
                    ldm4(bfr, baddr);
#pragma unroll
                    for (int mi = 0; mi < 2; mi++) {
                        mma16816h(acc[mi][nf2 * 2],     afr[mi], bfr[0], bfr[1]);
                        mma16816h(acc[mi][nf2 * 2 + 1], afr[mi], bfr[2], bfr[3]);
                    }
                }
            }
            __syncthreads();
        }

        // epilogue
#pragma unroll
        for (int mi = 0; mi < 2; mi++) {
#pragma unroll
            for (int nf = 0; nf < 8; nf++) {
                int row0 = m0 + warpM * 32 + mi * 16 + groupID;
                int col  = n0 + warpN * 64 + nf * 8 + tig * 2;
                if (row0 < N_NODES) {
                    float2 v0 = make_float2(acc[mi][nf][0], acc[mi][nf][1]);
                    *reinterpret_cast<float2*>(out + (size_t)row0 * OUT_DIM + col) = v0;
                }
                int row1 = row0 + 8;
                if (row1 < N_NODES) {
                    float2 v1 = make_float2(acc[mi][nf][2], acc[mi][nf][3]);
                    *reinterpret_cast<float2*>(out + (size_t)row1 * OUT_DIM + col) = v1;
                }
            }
        }
    }
}

// ---------------------------------------------------------------------------
extern "C" void kernel_launch(void* const* d_in, const int* in_sizes, int n_in,
                              void* d_out, int out_size) {
    const float* feature = (const float*)d_in[0];
    const float* weight  = (const float*)d_in[1];
    const int*   src     = (const int*)d_in[2];
    const int*   dst     = (const int*)d_in[3];
    float*       out     = (float*)d_out;
    const int n_edges = in_sizes[2];

    convw_zero_kernel<<<(IN_DIM * OUT_DIM + 255) / 256, 256>>>(weight);
    convf_hist_kernel<<<((N_NODES * IN_DIM / 8) + 255) / 256, 256>>>(feature, dst, n_edges);
    scanfill_kernel<<<PRE_NB, PRE_BLK>>>(src, dst, n_edges);
    // gather: 2 warps per node
    gather_kernel<<<(2 * N_NODES * 32 + 255) / 256, 256>>>();
    gemm_mma_kernel<<<296, 256>>>(out);
}